// round 11
// baseline (speedup 1.0000x reference)
#include <cuda_runtime.h>
#include <cuda_fp16.h>
#include <stdint.h>
#include <string.h>

// Problem constants
#define IN_F   2048
#define OUTF   512
#define NB     8
#define BATCH  16

// Packed bits: g_pkw[fb16][out*4+sub] : uint32. Bit pair (2j, 2j+1) holds the
// binarized weights for f = fb16*16 + j, columns out*8 + 2*sub + {0,1}.
// Independent of batch. Dims: 128 x 2048 = 262144 words = 1 MB.
__device__ uint32_t g_pkw[128 * 2048];

static __device__ __forceinline__ __half2 u2h2(uint32_t u) {
    __half2 h; memcpy(&h, &u, 4); return h;
}
static __device__ __forceinline__ uint32_t h22u(__half2 h) {
    uint32_t u; memcpy(&u, &h, 4); return u;
}

#define ONEU 0x3C003C00u   // half2 {1.0, 1.0}

// ---------------------------------------------------------------------------
// Pack kernel: binarize weight (>= 0.5), 2 bits per f (adjacent columns),
// 16 f per word. idx = fb16*2048 + (out*4 + sub); columns rem*2, rem*2+1.
// ---------------------------------------------------------------------------
__global__ void pack_kernel(const float* __restrict__ w) {
    int idx = blockIdx.x * blockDim.x + threadIdx.x;
    int fb16 = idx >> 11;         // f-chunk of 16
    int rem  = idx & 2047;        // out*4 + sub -> column base = rem*2
    const float2* wp = reinterpret_cast<const float2*>(w) + rem;
    uint32_t word = 0;
#pragma unroll
    for (int j = 0; j < 16; j++) {
        float2 v = __ldg(wp + (size_t)(fb16 * 16 + j) * 2048);
        word |= ((v.x >= 0.5f ? 1u : 0u) | (v.y >= 0.5f ? 2u : 0u)) << (2 * j);
    }
    g_pkw[idx] = word;
}

// ---------------------------------------------------------------------------
// Scan kernel. Thread sub in {0..3} owns lanes {2sub, 2sub+1} of row-pair
// (b0, b0+8): half2 state A = lane 2sub, B = lane 2sub+1 (each packs the two
// batch rows). CSA step per half2 -- 5 HFMA2 + 2 LOP, bit-exact vs R9:
//   a  = xu & m                                  (AND)
//   ga = ((gax ^ ONE) & m) ^ ONE                 (LOP3; == fma(a,-2,1) exactly,
//                                                 gax = fma(x,-2,1) in smem)
//   r  = fma(s, ga, a)                           r  = xor(s,a)
//   m1 = s*a
//   mj = fma(c, r, m1)                           mj = maj(s,a,c)
//   gc = fma(c,-2,1)
//   s' = fma(r, gc, c)                           s' = xor(r,c)
// Masks from sext of the packed word (pure ALU, no LUT LDS -- R10's mistake).
// SKEWED PIPELINE (as R8/R9): iteration i runs A-step(f=i-1) then B-step(f=i);
// cB(i)=mjA(i) same-iteration register; cA(i-1)=neighbor mjB(i-2) via a shfl
// issued 2 iterations earlier. (f,x,gax,mask) for the A-step arrive by
// register rotation. Both chains start from (s=0,c=0).
// Grid: 128 blocks x 128 threads = 512 warps = 1 warp/SMSP on 128 SMs.
// ---------------------------------------------------------------------------
__global__ void __launch_bounds__(128, 1)
scan_kernel(const float* __restrict__ x, float* __restrict__ out) {
    __shared__ uint32_t sxu[IN_F];  // {half(x[b0,f]), half(x[b0+8,f])}
    __shared__ uint32_t sgx[IN_F];  // fma(that, -2, 1)

    const int tid = threadIdx.x;
    const int blk = blockIdx.x;
    const int b0 = blk >> 4;                 // 0..7 ; pair row is b0+8
    const int out_base = (blk & 15) << 5;    // 32 outs per block

    const float* xa = x + b0 * IN_F;
    const float* xb = x + (b0 + 8) * IN_F;
    const __half2 neg2 = __float2half2_rn(-2.0f);
    const __half2 one  = __float2half2_rn(1.0f);
    const __half2 zero = __float2half2_rn(0.0f);
#pragma unroll
    for (int i = 0; i < IN_F / 128; i++) {
        int k = tid + i * 128;
        __half2 pr = __halves2half2(__float2half(xa[k]), __float2half(xb[k]));
        sxu[k] = h22u(pr);
        sgx[k] = h22u(__hfma2(pr, neg2, one));   // same op as in-loop ga
    }
    __syncthreads();

    const int sub  = tid & 3;
    const int lane = tid & 31;
    const int srcl = sub ? (lane - 1) : lane;       // carry source lane
    const uint32_t zmask = sub ? 0xFFFFFFFFu : 0u;  // lane-0 carry-in is 0
    const uint32_t* pk = g_pkw + out_base * 4 + tid;   // + fb16*2048 per chunk

    // sign-extend bit `b` of v to a full mask
    auto sext = [](uint32_t v, int b) {
        return (uint32_t)(((int32_t)(v << (31 - b))) >> 31);
    };

    __half2 sA = zero, sB = zero;
    uint32_t p1 = 0, p2 = 0;              // shfl pipeline: p2 is 2 iters old
    uint32_t mA_lag = 0, xu_lag = 0, gax_lag = 0;   // f = -1: a=0, ga=1 identity

    // One pipelined iteration: A-step(f-1) then B-step(f).
    auto stepAB = [&](uint32_t mB, uint32_t mAc, uint32_t xu, uint32_t gax) {
        // ---- A-step (f = i-1); cA = 2-iteration-old neighbor mjB ----
        __half2 cAv = u2h2(p2 & zmask);
        __half2 aA  = u2h2(xu_lag & mA_lag);
        __half2 gaA = u2h2(((gax_lag ^ ONEU) & mA_lag) ^ ONEU);
        __half2 rA  = __hfma2(sA, gaA, aA);
        __half2 m1A = __hmul2(sA, aA);
        __half2 mjA = __hfma2(cAv, rA, m1A);
        __half2 gcA = __hfma2(cAv, neg2, one);
        sA = __hfma2(rA, gcA, cAv);
        // ---- B-step (f = i); cB = mjA from THIS iteration ----
        __half2 aB  = u2h2(xu & mB);
        __half2 gaB = u2h2(((gax ^ ONEU) & mB) ^ ONEU);
        __half2 rB  = __hfma2(sB, gaB, aB);
        __half2 m1B = __hmul2(sB, aB);
        __half2 mjB = __hfma2(mjA, rB, m1B);
        __half2 gcB = __hfma2(mjA, neg2, one);
        sB = __hfma2(rB, gcB, mjA);
        // ---- carry exchange, consumed 2 iterations later ----
        p2 = p1;
        p1 = __shfl_sync(0xFFFFFFFFu, h22u(mjB), srcl);
        // ---- rotate f-state for next iteration's A-step ----
        mA_lag = mAc; xu_lag = xu; gax_lag = gax;
    };

    const uint4* sxu4 = reinterpret_cast<const uint4*>(sxu);
    const uint4* sgx4 = reinterpret_cast<const uint4*>(sgx);

    uint32_t w = __ldg(pk);

#pragma unroll 1
    for (int fb16 = 0; fb16 < 128; fb16++) {
        uint32_t wnext = 0;
        if (fb16 < 127) wnext = __ldg(pk + (fb16 + 1) * 2048);
        const uint4* px = sxu4 + fb16 * 4;
        const uint4* pg = sgx4 + fb16 * 4;
        uint4 x0 = px[0], x1 = px[1], x2 = px[2], x3 = px[3];
        uint4 g0 = pg[0], g1 = pg[1], g2 = pg[2], g3 = pg[3];
        stepAB(sext(w, 1),  sext(w, 0),  x0.x, g0.x);
        stepAB(sext(w, 3),  sext(w, 2),  x0.y, g0.y);
        stepAB(sext(w, 5),  sext(w, 4),  x0.z, g0.z);
        stepAB(sext(w, 7),  sext(w, 6),  x0.w, g0.w);
        stepAB(sext(w, 9),  sext(w, 8),  x1.x, g1.x);
        stepAB(sext(w, 11), sext(w, 10), x1.y, g1.y);
        stepAB(sext(w, 13), sext(w, 12), x1.z, g1.z);
        stepAB(sext(w, 15), sext(w, 14), x1.w, g1.w);
        stepAB(sext(w, 17), sext(w, 16), x2.x, g2.x);
        stepAB(sext(w, 19), sext(w, 18), x2.y, g2.y);
        stepAB(sext(w, 21), sext(w, 20), x2.z, g2.z);
        stepAB(sext(w, 23), sext(w, 22), x2.w, g2.w);
        stepAB(sext(w, 25), sext(w, 24), x3.x, g3.x);
        stepAB(sext(w, 27), sext(w, 26), x3.y, g3.y);
        stepAB(sext(w, 29), sext(w, 28), x3.z, g3.z);
        stepAB(sext(w, 31), sext(w, 30), x3.w, g3.w);
        w = wnext;
    }

    // Drain: final A-step (f = 2047). cA = p2 = shfl(mjB(2046)).
    __half2 cB_fin, cA_fin;
    {
        __half2 cAv = u2h2(p2 & zmask);
        __half2 aA  = u2h2(xu_lag & mA_lag);
        __half2 gaA = u2h2(((gax_lag ^ ONEU) & mA_lag) ^ ONEU);
        __half2 rA  = __hfma2(sA, gaA, aA);
        __half2 m1A = __hmul2(sA, aA);
        __half2 mjA = __hfma2(cAv, rA, m1A);
        __half2 gcA = __hfma2(cAv, neg2, one);
        sA = __hfma2(rA, gcA, cAv);
        cB_fin = mjA;                        // carry into lane 2sub+1
        cA_fin = u2h2(p1 & zmask);           // shfl(mjB(2047)) from last iter
    }

    // Output float32. Thread sub holds lanes (2sub, 2sub+1) of rows b0, b0+8.
    // s at out[b*4096 + o*8 + lane], c at +65536 floats.
    const int out_i = out_base + (tid >> 2);
    const int baseA = b0 * 4096 + out_i * 8 + 2 * sub;        // row b0
    const int baseB = baseA + 8 * 4096;                       // row b0+8
    float2 sAf = __half22float2(sA), cAf = __half22float2(cA_fin);
    float2 sBf = __half22float2(sB), cBf = __half22float2(cB_fin);
    out[baseA]             = sAf.x;   // row b0,   lane 2sub
    out[baseA + 1]         = sBf.x;   // row b0,   lane 2sub+1
    out[baseB]             = sAf.y;   // row b0+8, lane 2sub
    out[baseB + 1]         = sBf.y;
    out[65536 + baseA]     = cAf.x;
    out[65536 + baseA + 1] = cBf.x;
    out[65536 + baseB]     = cAf.y;
    out[65536 + baseB + 1] = cBf.y;
}

// ---------------------------------------------------------------------------
extern "C" void kernel_launch(void* const* d_in, const int* in_sizes, int n_in,
                              void* d_out, int out_size) {
    const float* x  = (const float*)d_in[0];   // (16, 2048) fp32
    const float* wt = (const float*)d_in[1];   // (2048, 4096) fp32
    float* out = (float*)d_out;                // 131072 fp32: [s | c]

    pack_kernel<<<1024, 256>>>(wt);
    scan_kernel<<<128, 128>>>(x, out);
}